// round 1
// baseline (speedup 1.0000x reference)
#include <cuda_runtime.h>
#include <math.h>

// Problem constants (fixed by the reference setup_inputs).
#define BB 8
#define NN 4096
#define DD 256

// Grid shape for the two streaming passes.
#define BPB 64               // blocks per batch
#define RPB (NN / BPB)       // 64 rows per block
#define RPW (RPB / 8)        // 8 rows per warp (8 warps/block)

// Device-global scratch (allocation-free contract).
__device__ float g_S[BB * DD];       // per-batch sum of normalized rows
__device__ float g_rnorm[BB * NN];   // per-row 1/max(||x||, 1e-12)
__device__ float g_bce;              // sum of BCE terms (pre-negation)

__global__ void zero_k() {
    int i = blockIdx.x * blockDim.x + threadIdx.x;
    if (i < BB * DD) g_S[i] = 0.0f;
    if (i == 0) g_bce = 0.0f;
}

// Pass 1: per-row norm + accumulate S_b = sum_n x_n / ||x_n||.
__global__ __launch_bounds__(256) void pass1(const float* __restrict__ x) {
    const int b    = blockIdx.y;
    const int wid  = threadIdx.x >> 5;
    const int lane = threadIdx.x & 31;
    const float* xb = x + (size_t)b * NN * DD;
    const int row0 = blockIdx.x * RPB + wid * RPW;

    float4 a0 = make_float4(0.f, 0.f, 0.f, 0.f);
    float4 a1 = make_float4(0.f, 0.f, 0.f, 0.f);

    #pragma unroll
    for (int r = 0; r < RPW; ++r) {
        const int row = row0 + r;
        const float4* p = reinterpret_cast<const float4*>(xb + (size_t)row * DD);
        float4 v0 = p[lane];        // d = lane*4 .. lane*4+3
        float4 v1 = p[lane + 32];   // d = 128 + lane*4 ..

        float ss = v0.x * v0.x + v0.y * v0.y + v0.z * v0.z + v0.w * v0.w
                 + v1.x * v1.x + v1.y * v1.y + v1.z * v1.z + v1.w * v1.w;
        #pragma unroll
        for (int o = 16; o > 0; o >>= 1)
            ss += __shfl_xor_sync(0xffffffffu, ss, o);

        float rn = 1.0f / fmaxf(sqrtf(ss), 1e-12f);
        if (lane == 0) g_rnorm[b * NN + row] = rn;

        a0.x += v0.x * rn; a0.y += v0.y * rn; a0.z += v0.z * rn; a0.w += v0.w * rn;
        a1.x += v1.x * rn; a1.y += v1.y * rn; a1.z += v1.z * rn; a1.w += v1.w * rn;
    }

    // Reduce the 8 warp-local partial S vectors, then one atomicAdd per element.
    __shared__ float4 sS[8][64];   // [warp][lane-chunk] ; lane owns chunks lane & lane+32
    sS[wid][lane] = a0;
    sS[wid][lane + 32] = a1;
    __syncthreads();

    const int t = threadIdx.x;          // 0..255 -> one d-chunk column of 4? No: 64 float4 = 256 floats
    // Each thread t sums one float across warps: view sS as float[8][256].
    const float* sSf = reinterpret_cast<const float*>(sS);
    float s = 0.f;
    #pragma unroll
    for (int w = 0; w < 8; ++w) s += sSf[w * DD + t];
    atomicAdd(&g_S[b * DD + t], s);
}

// Pass 2: per-row dot with S_b -> target -> BCE term, reduced to g_bce.
__global__ __launch_bounds__(256) void pass2(const float* __restrict__ x,
                                             const float* __restrict__ sc) {
    const int b = blockIdx.y;
    __shared__ float sS[DD];
    __shared__ float sAcc;
    sS[threadIdx.x] = g_S[b * DD + threadIdx.x];
    if (threadIdx.x == 0) sAcc = 0.0f;
    __syncthreads();

    const int wid  = threadIdx.x >> 5;
    const int lane = threadIdx.x & 31;
    const float4* sS4 = reinterpret_cast<const float4*>(sS);
    const float4 w0 = sS4[lane];
    const float4 w1 = sS4[lane + 32];

    const float* xb = x + (size_t)b * NN * DD;
    const int row0 = blockIdx.x * RPB + wid * RPW;
    float local = 0.0f;

    #pragma unroll
    for (int r = 0; r < RPW; ++r) {
        const int row = row0 + r;
        const float4* p = reinterpret_cast<const float4*>(xb + (size_t)row * DD);
        float4 v0 = p[lane];
        float4 v1 = p[lane + 32];

        float d = v0.x * w0.x + v0.y * w0.y + v0.z * w0.z + v0.w * w0.w
                + v1.x * w1.x + v1.y * w1.y + v1.z * w1.z + v1.w * w1.w;
        #pragma unroll
        for (int o = 16; o > 0; o >>= 1)
            d += __shfl_xor_sync(0xffffffffu, d, o);

        if (lane == 0) {
            const float rn  = g_rnorm[b * NN + row];
            const float sim = (d * rn - 1.0f) * (1.0f / (float)(NN - 1));
            const float tgt = 1.0f - fmaxf(sim, 0.0f);
            const float s   = sc[b * NN + row];
            const float ls  = fmaxf(logf(s),    -100.0f);
            const float l1  = fmaxf(log1pf(-s), -100.0f);
            local += tgt * ls + (1.0f - tgt) * l1;
        }
    }

    if (lane == 0) atomicAdd(&sAcc, local);
    __syncthreads();
    if (threadIdx.x == 0) atomicAdd(&g_bce, sAcc);
}

// Epilogue: feat_loss from ||S_b||^2 (Gram identity) + combine with BCE mean.
__global__ void finalize_k(float* __restrict__ out) {
    __shared__ float red[256];
    const int t = threadIdx.x;
    float v = 0.f;
    #pragma unroll
    for (int b = 0; b < BB; ++b) {
        const float s = g_S[b * DD + t];
        v += s * s;
    }
    red[t] = v;
    __syncthreads();
    for (int o = 128; o > 0; o >>= 1) {
        if (t < o) red[t] += red[t + o];
        __syncthreads();
    }
    if (t == 0) {
        const float bce  = -g_bce / (float)(BB * NN);
        const float feat = 1.0f - red[0] / ((float)BB * (float)NN * (float)NN);
        out[0] = bce + feat;
    }
}

extern "C" void kernel_launch(void* const* d_in, const int* in_sizes, int n_in,
                              void* d_out, int out_size) {
    const float* feats  = (const float*)d_in[0];   // [B, N, D] f32
    const float* scores = (const float*)d_in[1];   // [B, N, 1] f32
    float* out = (float*)d_out;

    zero_k<<<(BB * DD + 255) / 256, 256>>>();
    dim3 grid(BPB, BB);
    pass1<<<grid, 256>>>(feats);
    pass2<<<grid, 256>>>(feats, scores);
    finalize_k<<<1, 256>>>(out);
}